// round 16
// baseline (speedup 1.0000x reference)
#include <cuda_runtime.h>

// Column-wise L2 normalization: u[d] = sum_n x[n,d]^2 + eps; out = x * rsqrt(u)
// x: [32768, 2048] fp32 row-major.
//
// Persistent kernel, 4 column stripes of 512 cols (64 MB, fits ~126 MB L2).
// R15 change: fuse phase B(s) (L2-hit read + streaming store) with phase
// A(s+1) (DRAM read + reduce) so DRAM read and write streams overlap instead
// of alternating. Pipeline: A(0); bar; { inv(s); B(s)+A(s+1); bar } x3;
// inv(3); B(3). Same 4 barriers, double-buffered partials.

#define NCTAS     148
#define TPB       1024
#define DV        512            // D/4 (float4 per full row)
#define NROWS     32768
#define NSTRIPES  4
#define SCOLS     512            // columns per stripe
#define SVEC      128            // float4 groups per stripe row
#define NPH       8              // row phases per CTA (TPB / SVEC)
#define ROWSTRIDE (NPH * NCTAS)  // 1184
#define STEP      (ROWSTRIDE * DV)
#define CHALF     74             // NCTAS / 2 per reducing thread
#define R27LIM    800            // r0 < 800 <=> iteration k=27 in-bounds

__device__ float g_partial[2][NCTAS * SCOLS]; // double-buffered partials
__device__ unsigned int g_bar_count;
__device__ unsigned int g_bar_gen;

// Self-resetting grid barrier; all 148 CTAs co-resident (1 CTA/SM).
__device__ __forceinline__ void grid_barrier() {
    __threadfence();
    __syncthreads();
    if (threadIdx.x == 0) {
        unsigned int target = *(volatile unsigned int*)&g_bar_gen + 1u;
        unsigned int arrived = atomicAdd(&g_bar_count, 1u);
        if (arrived == NCTAS - 1) {
            atomicExch(&g_bar_count, 0u);
            __threadfence();
            atomicAdd(&g_bar_gen, 1u);
        } else {
            while ((int)(*(volatile unsigned int*)&g_bar_gen - target) < 0)
                __nanosleep(64);
        }
        __threadfence();
    }
    __syncthreads();
}

__global__ __launch_bounds__(TPB, 1)
void colnorm_kernel(const float* __restrict__ x, float* __restrict__ out) {
    const int tid    = threadIdx.x;
    const int b      = blockIdx.x;
    const int col4   = tid & (SVEC - 1);       // float4 group within stripe
    const int rphase = tid >> 7;               // row phase (0..7)
    const int r0     = b + rphase * NCTAS;     // first row for this thread
    const bool has27 = (r0 < R27LIM);

    __shared__ float4 sred[NPH * SVEC];        // 16 KB
    __shared__ float  spart[2 * SCOLS];        // 4 KB
    __shared__ float  sinv[SCOLS];             // 2 KB

    const float4* __restrict__ x4 = (const float4*)x;
    float4* __restrict__       o4 = (float4*)out;

    // ================= Phase A for stripe 0 (pure reduce) =================
    {
        const int base = 0 * SVEC + col4;
        float4 acc = make_float4(0.f, 0.f, 0.f, 0.f);
        int idx = r0 * DV + base;
        #pragma unroll
        for (int t = 0; t < 3; ++t) {
            float4 v[8];
            #pragma unroll
            for (int j = 0; j < 8; ++j) v[j] = x4[idx + j * STEP];
            #pragma unroll
            for (int j = 0; j < 8; ++j) {
                acc.x += v[j].x * v[j].x; acc.y += v[j].y * v[j].y;
                acc.z += v[j].z * v[j].z; acc.w += v[j].w * v[j].w;
            }
            idx += 8 * STEP;
        }
        float4 v[4];
        v[0] = x4[idx];
        v[1] = x4[idx + STEP];
        v[2] = x4[idx + 2 * STEP];
        v[3] = has27 ? x4[idx + 3 * STEP] : make_float4(0.f, 0.f, 0.f, 0.f);
        #pragma unroll
        for (int j = 0; j < 4; ++j) {
            acc.x += v[j].x * v[j].x; acc.y += v[j].y * v[j].y;
            acc.z += v[j].z * v[j].z; acc.w += v[j].w * v[j].w;
        }
        sred[rphase * SVEC + col4] = acc;
    }
    __syncthreads();
    if (tid < SCOLS) {
        const float* sf = (const float*)sred;
        float v = sf[tid];
        #pragma unroll
        for (int k = 1; k < NPH; ++k) v += sf[k * SCOLS + tid];
        g_partial[0][b * SCOLS + tid] = v;
    }
    grid_barrier();

    // ================= Main loop over stripes =================
    for (int s = 0; s < NSTRIPES; ++s) {
        const float* __restrict__ gp = g_partial[s & 1];

        // ---- Final reduce across CTAs for stripe s: 2 threads/column ----
        {
            const int col  = tid & (SCOLS - 1);
            const int half = tid >> 9;
            const int c0   = half * CHALF;
            float sum = 0.f;
            #pragma unroll 8
            for (int c = 0; c < CHALF; ++c)
                sum += __ldcg(&gp[(c0 + c) * SCOLS + col]);
            spart[half * SCOLS + col] = sum;
        }
        __syncthreads();
        if (tid < SCOLS)
            sinv[tid] = rsqrtf(spart[tid] + spart[SCOLS + tid] + 1e-6f);
        __syncthreads();
        const float4 inv = ((const float4*)sinv)[col4];

        if (s < NSTRIPES - 1) {
            // ---- Fused: B(s) [L2-hit read + .cs store] + A(s+1) [DRAM read] ----
            const int baseB = s * SVEC + col4;
            const int baseA = (s + 1) * SVEC + col4;
            int idxA = r0 * DV + baseA;
            int idxB = r0 * DV + baseB;
            float4 acc = make_float4(0.f, 0.f, 0.f, 0.f);
            #pragma unroll
            for (int t = 0; t < 6; ++t) {       // 6 batches of 4 = 24 iters
                float4 a[4], w[4];
                #pragma unroll
                for (int j = 0; j < 4; ++j) a[j] = x4[idxA + j * STEP];
                #pragma unroll
                for (int j = 0; j < 4; ++j) w[j] = __ldcs(&x4[idxB + j * STEP]);
                #pragma unroll
                for (int j = 0; j < 4; ++j) {
                    acc.x += a[j].x * a[j].x; acc.y += a[j].y * a[j].y;
                    acc.z += a[j].z * a[j].z; acc.w += a[j].w * a[j].w;
                }
                #pragma unroll
                for (int j = 0; j < 4; ++j) {
                    float4 o;
                    o.x = w[j].x * inv.x; o.y = w[j].y * inv.y;
                    o.z = w[j].z * inv.z; o.w = w[j].w * inv.w;
                    __stcs(&o4[idxB + j * STEP], o);
                }
                idxA += 4 * STEP;
                idxB += 4 * STEP;
            }
            // Tail: iters 24,25,26 unconditional + 27 predicated.
            {
                float4 a[4], w[4];
                a[0] = x4[idxA];
                a[1] = x4[idxA + STEP];
                a[2] = x4[idxA + 2 * STEP];
                a[3] = has27 ? x4[idxA + 3 * STEP] : make_float4(0.f, 0.f, 0.f, 0.f);
                w[0] = __ldcs(&x4[idxB]);
                w[1] = __ldcs(&x4[idxB + STEP]);
                w[2] = __ldcs(&x4[idxB + 2 * STEP]);
                if (has27) w[3] = __ldcs(&x4[idxB + 3 * STEP]);
                #pragma unroll
                for (int j = 0; j < 4; ++j) {
                    acc.x += a[j].x * a[j].x; acc.y += a[j].y * a[j].y;
                    acc.z += a[j].z * a[j].z; acc.w += a[j].w * a[j].w;
                }
                #pragma unroll
                for (int j = 0; j < 3; ++j) {
                    float4 o;
                    o.x = w[j].x * inv.x; o.y = w[j].y * inv.y;
                    o.z = w[j].z * inv.z; o.w = w[j].w * inv.w;
                    __stcs(&o4[idxB + j * STEP], o);
                }
                if (has27) {
                    float4 o;
                    o.x = w[3].x * inv.x; o.y = w[3].y * inv.y;
                    o.z = w[3].z * inv.z; o.w = w[3].w * inv.w;
                    __stcs(&o4[idxB + 3 * STEP], o);
                }
            }
            // Fold and publish partials for stripe s+1.
            sred[rphase * SVEC + col4] = acc;
            __syncthreads();
            if (tid < SCOLS) {
                const float* sf = (const float*)sred;
                float v = sf[tid];
                #pragma unroll
                for (int k = 1; k < NPH; ++k) v += sf[k * SCOLS + tid];
                g_partial[(s + 1) & 1][b * SCOLS + tid] = v;
            }
            grid_barrier();
        } else {
            // ---- Plain phase B for the last stripe ----
            const int baseB = s * SVEC + col4;
            int idx = r0 * DV + baseB;
            #pragma unroll
            for (int t = 0; t < 3; ++t) {
                float4 v[8];
                #pragma unroll
                for (int j = 0; j < 8; ++j) v[j] = __ldcs(&x4[idx + j * STEP]);
                #pragma unroll
                for (int j = 0; j < 8; ++j) {
                    float4 o;
                    o.x = v[j].x * inv.x; o.y = v[j].y * inv.y;
                    o.z = v[j].z * inv.z; o.w = v[j].w * inv.w;
                    __stcs(&o4[idx + j * STEP], o);
                }
                idx += 8 * STEP;
            }
            float4 v[4];
            v[0] = __ldcs(&x4[idx]);
            v[1] = __ldcs(&x4[idx + STEP]);
            v[2] = __ldcs(&x4[idx + 2 * STEP]);
            if (has27) v[3] = __ldcs(&x4[idx + 3 * STEP]);
            #pragma unroll
            for (int j = 0; j < 3; ++j) {
                float4 o;
                o.x = v[j].x * inv.x; o.y = v[j].y * inv.y;
                o.z = v[j].z * inv.z; o.w = v[j].w * inv.w;
                __stcs(&o4[idx + j * STEP], o);
            }
            if (has27) {
                float4 o;
                o.x = v[3].x * inv.x; o.y = v[3].y * inv.y;
                o.z = v[3].z * inv.z; o.w = v[3].w * inv.w;
                __stcs(&o4[idx + 3 * STEP], o);
            }
        }
    }
}

extern "C" void kernel_launch(void* const* d_in, const int* in_sizes, int n_in,
                              void* d_out, int out_size) {
    const float* x = (const float*)d_in[0];
    float* out = (float*)d_out;
    colnorm_kernel<<<NCTAS, TPB>>>(x, out);
}

// round 17
// speedup vs baseline: 1.0756x; 1.0756x over previous
#include <cuda_runtime.h>

// Column-wise L2 normalization: u[d] = sum_n x[n,d]^2 + eps; out = x * rsqrt(u)
// x: [32768, 2048] fp32 row-major.
//
// Persistent kernel; 8 column stripes of 256 cols (32 MB each). Fused
// pipeline: phase B(s) (L2-hit .cs read + .cs store) runs concurrently with
// phase A(s+1) (DRAM read + reduce), so DRAM read and write streams overlap.
// R16 fix over R15: stripe size halved (64->32 MB) so the fused working set
// (consume 32 MB + fill 32 MB) fits L2 (~126 MB) -> reuse preserved.
// Pipeline: A(0); bar; { inv(s); B(s)+A(s+1); bar } x7; inv(7); B(7).

#define NCTAS     148
#define TPB       1024
#define DV        512            // D/4 (float4 per full row)
#define NROWS     32768
#define NSTRIPES  8
#define SCOLS     256            // columns per stripe
#define SVEC      64             // float4 groups per stripe row
#define NPH       16             // row phases per CTA (TPB / SVEC)
#define ROWSTRIDE (NPH * NCTAS)  // 2368
#define STEP      (ROWSTRIDE * DV)
#define CQUART    37             // NCTAS / 4 per reducing thread
#define R13LIM    1984           // r0 < 1984 <=> iteration k=13 in-bounds

__device__ float g_partial[2][NCTAS * SCOLS]; // double-buffered partials
__device__ unsigned int g_bar_count;
__device__ unsigned int g_bar_gen;

// Self-resetting grid barrier; all 148 CTAs co-resident (1 CTA/SM).
__device__ __forceinline__ void grid_barrier() {
    __threadfence();
    __syncthreads();
    if (threadIdx.x == 0) {
        unsigned int target = *(volatile unsigned int*)&g_bar_gen + 1u;
        unsigned int arrived = atomicAdd(&g_bar_count, 1u);
        if (arrived == NCTAS - 1) {
            atomicExch(&g_bar_count, 0u);
            __threadfence();
            atomicAdd(&g_bar_gen, 1u);
        } else {
            while ((int)(*(volatile unsigned int*)&g_bar_gen - target) < 0)
                __nanosleep(64);
        }
        __threadfence();
    }
    __syncthreads();
}

__global__ __launch_bounds__(TPB, 1)
void colnorm_kernel(const float* __restrict__ x, float* __restrict__ out) {
    const int tid    = threadIdx.x;
    const int b      = blockIdx.x;
    const int col4   = tid & (SVEC - 1);       // float4 group within stripe
    const int rphase = tid >> 6;               // row phase (0..15)
    const int r0     = b + rphase * NCTAS;     // first row for this thread
    const bool has13 = (r0 < R13LIM);

    __shared__ float4 sred[NPH * SVEC];        // 16 KB (16 phases x 64 groups)
    __shared__ float  spart[4 * SCOLS];        // 4 KB: 4-way reduce quarters
    __shared__ float  sinv[SCOLS];             // 1 KB

    const float4* __restrict__ x4 = (const float4*)x;
    float4* __restrict__       o4 = (float4*)out;

    // ================= Phase A for stripe 0 (pure reduce) =================
    {
        const int base = col4;                 // stripe 0
        float4 acc = make_float4(0.f, 0.f, 0.f, 0.f);
        int idx = r0 * DV + base;
        #pragma unroll
        for (int t = 0; t < 3; ++t) {          // k = 0..11
            float4 v[4];
            #pragma unroll
            for (int j = 0; j < 4; ++j) v[j] = x4[idx + j * STEP];
            #pragma unroll
            for (int j = 0; j < 4; ++j) {
                acc.x += v[j].x * v[j].x; acc.y += v[j].y * v[j].y;
                acc.z += v[j].z * v[j].z; acc.w += v[j].w * v[j].w;
            }
            idx += 4 * STEP;
        }
        float4 v0 = x4[idx];                   // k = 12 (always valid)
        float4 v1 = has13 ? x4[idx + STEP]     // k = 13 (predicated)
                          : make_float4(0.f, 0.f, 0.f, 0.f);
        acc.x += v0.x * v0.x + v1.x * v1.x;
        acc.y += v0.y * v0.y + v1.y * v1.y;
        acc.z += v0.z * v0.z + v1.z * v1.z;
        acc.w += v0.w * v0.w + v1.w * v1.w;
        sred[rphase * SVEC + col4] = acc;
    }
    __syncthreads();
    if (tid < SCOLS) {
        const float* sf = (const float*)sred;  // [NPH][SCOLS]
        float v = sf[tid];
        #pragma unroll
        for (int k = 1; k < NPH; ++k) v += sf[k * SCOLS + tid];
        g_partial[0][b * SCOLS + tid] = v;
    }
    grid_barrier();

    // ================= Main loop over stripes =================
    for (int s = 0; s < NSTRIPES; ++s) {
        const float* __restrict__ gp = g_partial[s & 1];

        // ---- Final reduce across CTAs for stripe s: 4 threads/column ----
        {
            const int col = tid & (SCOLS - 1);
            const int q   = tid >> 8;                   // 0..3
            const int c0  = q * CQUART;
            float sum = 0.f;
            #pragma unroll
            for (int c = 0; c < CQUART; ++c)
                sum += __ldcg(&gp[(c0 + c) * SCOLS + col]);
            spart[q * SCOLS + col] = sum;
        }
        __syncthreads();
        if (tid < SCOLS)
            sinv[tid] = rsqrtf(spart[tid] + spart[SCOLS + tid] +
                               spart[2 * SCOLS + tid] + spart[3 * SCOLS + tid] +
                               1e-6f);
        __syncthreads();
        const float4 inv = ((const float4*)sinv)[col4];

        if (s < NSTRIPES - 1) {
            // ---- Fused: B(s) [L2 .cs read + .cs store] + A(s+1) [DRAM read] ----
            const int baseB = s * SVEC + col4;
            const int baseA = (s + 1) * SVEC + col4;
            int idxA = r0 * DV + baseA;
            int idxB = r0 * DV + baseB;
            float4 acc = make_float4(0.f, 0.f, 0.f, 0.f);
            #pragma unroll
            for (int t = 0; t < 3; ++t) {      // k = 0..11
                float4 a[4], w[4];
                #pragma unroll
                for (int j = 0; j < 4; ++j) a[j] = x4[idxA + j * STEP];
                #pragma unroll
                for (int j = 0; j < 4; ++j) w[j] = __ldcs(&x4[idxB + j * STEP]);
                #pragma unroll
                for (int j = 0; j < 4; ++j) {
                    acc.x += a[j].x * a[j].x; acc.y += a[j].y * a[j].y;
                    acc.z += a[j].z * a[j].z; acc.w += a[j].w * a[j].w;
                }
                #pragma unroll
                for (int j = 0; j < 4; ++j) {
                    float4 o;
                    o.x = w[j].x * inv.x; o.y = w[j].y * inv.y;
                    o.z = w[j].z * inv.z; o.w = w[j].w * inv.w;
                    __stcs(&o4[idxB + j * STEP], o);
                }
                idxA += 4 * STEP;
                idxB += 4 * STEP;
            }
            {   // Tail: k = 12 unconditional, k = 13 predicated.
                float4 a0 = x4[idxA];
                float4 a1 = has13 ? x4[idxA + STEP]
                                  : make_float4(0.f, 0.f, 0.f, 0.f);
                float4 w0 = __ldcs(&x4[idxB]);
                float4 w1;
                if (has13) w1 = __ldcs(&x4[idxB + STEP]);
                acc.x += a0.x * a0.x + a1.x * a1.x;
                acc.y += a0.y * a0.y + a1.y * a1.y;
                acc.z += a0.z * a0.z + a1.z * a1.z;
                acc.w += a0.w * a0.w + a1.w * a1.w;
                float4 o;
                o.x = w0.x * inv.x; o.y = w0.y * inv.y;
                o.z = w0.z * inv.z; o.w = w0.w * inv.w;
                __stcs(&o4[idxB], o);
                if (has13) {
                    o.x = w1.x * inv.x; o.y = w1.y * inv.y;
                    o.z = w1.z * inv.z; o.w = w1.w * inv.w;
                    __stcs(&o4[idxB + STEP], o);
                }
            }
            // Fold and publish partials for stripe s+1.
            sred[rphase * SVEC + col4] = acc;
            __syncthreads();
            if (tid < SCOLS) {
                const float* sf = (const float*)sred;
                float v = sf[tid];
                #pragma unroll
                for (int k = 1; k < NPH; ++k) v += sf[k * SCOLS + tid];
                g_partial[(s + 1) & 1][b * SCOLS + tid] = v;
            }
            grid_barrier();
        } else {
            // ---- Plain phase B for the last stripe ----
            const int baseB = s * SVEC + col4;
            int idx = r0 * DV + baseB;
            #pragma unroll
            for (int t = 0; t < 3; ++t) {      // k = 0..11
                float4 v[4];
                #pragma unroll
                for (int j = 0; j < 4; ++j) v[j] = __ldcs(&x4[idx + j * STEP]);
                #pragma unroll
                for (int j = 0; j < 4; ++j) {
                    float4 o;
                    o.x = v[j].x * inv.x; o.y = v[j].y * inv.y;
                    o.z = v[j].z * inv.z; o.w = v[j].w * inv.w;
                    __stcs(&o4[idx + j * STEP], o);
                }
                idx += 4 * STEP;
            }
            float4 w0 = __ldcs(&x4[idx]);
            float4 o;
            o.x = w0.x * inv.x; o.y = w0.y * inv.y;
            o.z = w0.z * inv.z; o.w = w0.w * inv.w;
            __stcs(&o4[idx], o);
            if (has13) {
                float4 w1 = __ldcs(&x4[idx + STEP]);
                o.x = w1.x * inv.x; o.y = w1.y * inv.y;
                o.z = w1.z * inv.z; o.w = w1.w * inv.w;
                __stcs(&o4[idx + STEP], o);
            }
        }
    }
}

extern "C" void kernel_launch(void* const* d_in, const int* in_sizes, int n_in,
                              void* d_out, int out_size) {
    const float* x = (const float*)d_in[0];
    float* out = (float*)d_out;
    colnorm_kernel<<<NCTAS, TPB>>>(x, out);
}